// round 2
// baseline (speedup 1.0000x reference)
#include <cuda_runtime.h>

#define HH 480
#define WW 640
#define NC 3
#define SKIP 5
#define PH 96            // HH/SKIP
#define PW 128           // WW/SKIP
#define NP (PH*PW)       // 12288 sampled pixels
#define BH 60            // bin rows   (GRID=8, start 4)
#define BWID 80          // bin cols
#define NB (BH*BWID)     // 4800 bins
#define BPT 8            // bins per thread (same bin row)
#define CPG (BWID/BPT)   // 10 col-groups per bin row
#define NTH (BH*CPG)     // 600 worker threads (bin side)
#define BGRID 3          // ceil(600/256)
#define PSPLIT 98        // pixel-slice CTAs -> 3*98 = 294 CTAs (~2/SM)

// ---------- device scratch (no allocations allowed) ----------
__device__ float g_px[2*NP];
__device__ float g_py[2*NP];
__device__ float g_ux[2*NP];   // 2*ux
__device__ float g_uy[2*NP];   // 2*uy
__device__ float g_dd[2*NP];   // dist
__device__ int   g_n[2];       // compacted counts per class segment (class 1,2)
__device__ int   g_cnt[NC];    // raw label counts (incl. class 0)
__device__ float g_dsum[2*NB]; // dsum rows for class 1,2
__device__ float g_rois_scratch[NC*6];
__device__ float g_hough_scratch[NC*NB];

// ---------- kernel 0: zero accumulators ----------
__global__ void init_k(float* __restrict__ hough) {
    int i = blockIdx.x * blockDim.x + threadIdx.x;
    if (i < NC*NB) hough[i] = 0.0f;
    if (i < 2*NB)  g_dsum[i] = 0.0f;
    if (i < 2)     g_n[i] = 0;
    if (i < NC)    g_cnt[i] = 0;
}

// ---------- kernel 1: gather + compact sampled pixels ----------
__global__ void prep_k(const int* __restrict__ label,
                       const float* __restrict__ vert) {
    int i = blockIdx.x * blockDim.x + threadIdx.x;
    if (i >= NP) return;
    int r = i / PW, c = i % PW;
    int vy = r * SKIP, vx = c * SKIP;
    int vl = label[vy * WW + vx];
    atomicAdd(&g_cnt[vl], 1);
    if (vl > 0) {
        int seg  = vl - 1;
        int slot = atomicAdd(&g_n[seg], 1) + seg * NP;
        int base = (vl * 3) * (HH * WW) + vy * WW + vx;
        g_px[slot] = (float)vx;
        g_py[slot] = (float)vy;
        g_ux[slot] = 2.0f * vert[base];
        g_uy[slot] = 2.0f * vert[base + HH * WW];
        g_dd[slot] = vert[base + 2 * HH * WW];
    }
}

// ---------- kernel 2: pairwise voting ----------
// grid (BGRID, PSPLIT), block 256. Each thread owns 8 consecutive bins in one bin row.
__global__ void __launch_bounds__(256, 2)
vote_k(float* __restrict__ hough) {
    __shared__ float s_px[256], s_py[256], s_ux[256], s_uy[256], s_dd[256];

    int tid = threadIdx.x;
    int gt  = blockIdx.x * 256 + tid;
    bool active = gt < NTH;
    int binrow = active ? gt / CPG : 0;
    int colg   = active ? gt % CPG : 0;
    float byf  = 4.0f + 8.0f * (float)binrow;
    float bx0  = 4.0f + 8.0f * (float)(colg * BPT);

    for (int seg = 0; seg < 2; seg++) {
        int n     = g_n[seg];
        int chunk = (n + PSPLIT - 1) / PSPLIT;
        int start = blockIdx.y * chunk;
        int end   = min(start + chunk, n);

        float aH[BPT], aD[BPT];
        #pragma unroll
        for (int b = 0; b < BPT; b++) { aH[b] = 0.f; aD[b] = 0.f; }

        for (int t = start; t < end; t += 256) {
            int m = min(256, end - t);
            __syncthreads();
            if (tid < m) {
                int s = seg * NP + t + tid;
                s_px[tid] = g_px[s];
                s_py[tid] = g_py[s];
                s_ux[tid] = g_ux[s];
                s_uy[tid] = g_uy[s];
                s_dd[tid] = g_dd[s];
            }
            __syncthreads();

            #pragma unroll 2
            for (int j = 0; j < m; j++) {
                float px = s_px[j], py = s_py[j];
                float ux = s_ux[j], uy = s_uy[j];
                float dd = s_dd[j];
                float ddy = byf - py;
                float t2  = fmaf(ddy, ddy, 1e-6f);   // ddy^2 + eps
                float dyu = ddy * uy;                // ddy * 2uy
                #pragma unroll
                for (int b = 0; b < BPT; b++) {
                    float ddx = (bx0 + 8.0f * (float)b) - px;
                    float nxy = fmaf(ddx, ddx, t2);     // ddx^2+ddy^2+eps (>0)
                    float dot = fmaf(ddx, ux, dyu);     // 2*(ddx*ux+ddy*uy)
                    // dot>0 && dot^2>nxy  <=>  dot*|dot| > nxy   (nxy>0)
                    bool  ok  = (dot * fabsf(dot)) > nxy;
                    aH[b] += ok ? 1.0f : 0.0f;
                    aD[b] += ok ? dd   : 0.0f;
                }
            }
        }

        if (active) {
            int binbase = binrow * BWID + colg * BPT;
            #pragma unroll
            for (int b = 0; b < BPT; b++) {
                if (aH[b] != 0.0f) {
                    atomicAdd(&hough[(seg + 1) * NB + binbase + b], aH[b]);
                    atomicAdd(&g_dsum[seg * NB + binbase + b], aD[b]);
                }
            }
        }
        __syncthreads();
    }
}

// ---------- kernel 3: argmax + ROI epilogue (3 CTAs, one per class) ----------
__global__ void finish_k(const float* __restrict__ hough,
                         float* __restrict__ rois,
                         const float* __restrict__ meta,
                         const float* __restrict__ extents) {
    __shared__ float sv[256];
    __shared__ int   si[256];
    int c   = blockIdx.x;
    int tid = threadIdx.x;

    if (c > 0) {
        // batched loads -> high MLP (19 independent LDGs in flight)
        float best = -1.0f; int bi = 0;
        #pragma unroll
        for (int k = 0; k < 19; k++) {
            int i = tid + k * 256;
            float v = (i < NB) ? hough[c * NB + i] : -2.0f;
            if (v > best) { best = v; bi = i; }   // ascending i -> first max kept
        }
        sv[tid] = best; si[tid] = bi;
        __syncthreads();
        #pragma unroll
        for (int s = 128; s > 0; s >>= 1) {
            if (tid < s) {
                float v2 = sv[tid + s]; int i2 = si[tid + s];
                if (v2 > sv[tid] || (v2 == sv[tid] && i2 < si[tid])) {
                    sv[tid] = v2; si[tid] = i2;
                }
            }
            __syncthreads();
        }
    }

    if (tid == 0) {
        int peak; float votes;
        if (c == 0) { peak = 0; votes = 0.0f; }   // class-0 hough row is identically 0
        else        { peak = si[0]; votes = sv[0]; }
        float ds    = (c > 0) ? g_dsum[(c - 1) * NB + peak] : 0.0f;
        float depth = ds / fmaxf(votes, 1.0f);
        float cx = 4.0f + 8.0f * (float)(peak % BWID);
        float cy = 4.0f + 8.0f * (float)(peak / BWID);
        float cnt = (float)g_cnt[c];
        float score = votes / fmaxf(cnt, 1.0f);
        bool  valid = (cnt > 5.0f) && (score > 0.3f);
        float fx = meta[0], fy = meta[4];
        float e0 = extents[c*3+0], e1 = extents[c*3+1], e2 = extents[c*3+2];
        float diag = sqrtf(e0*e0 + e1*e1 + e2*e2);
        float sz = fmaxf(fabsf(depth), 0.001f);
        float bw = fabsf(diag * fx) / sz;
        float bh = fabsf(diag * fy) / sz;
        rois[c*6+0] = (float)c;
        rois[c*6+1] = cx - bw * 0.5f;
        rois[c*6+2] = cy - bh * 0.5f;
        rois[c*6+3] = cx + bw * 0.5f;
        rois[c*6+4] = cy + bh * 0.5f;
        rois[c*6+5] = valid ? score : 0.0f;
    }
}

extern "C" void kernel_launch(void* const* d_in, const int* in_sizes, int n_in,
                              void* d_out, int out_size) {
    const int*   label = (const int*)  d_in[0];
    const float* vert  = (const float*)d_in[1];
    const float* meta  = (const float*)d_in[2];
    const float* ext   = (const float*)d_in[3];
    float* out = (float*)d_out;

    // Output is the flattened tuple (rois[3,6], hough[3,4800]) -> 18 + 14400.
    float *rois_p, *hough_p;
    if (out_size >= NC*6 + NC*NB) {
        rois_p = out; hough_p = out + NC*6;
    } else if (out_size >= NC*NB) {
        void* tmp = nullptr;
        cudaGetSymbolAddress(&tmp, g_rois_scratch);
        rois_p = (float*)tmp; hough_p = out;
    } else {
        void* tmp = nullptr;
        cudaGetSymbolAddress(&tmp, g_hough_scratch);
        rois_p = out; hough_p = (float*)tmp;
    }

    init_k<<<(NC*NB + 255) / 256, 256>>>(hough_p);
    prep_k<<<(NP + 255) / 256, 256>>>(label, vert);
    dim3 vgrid(BGRID, PSPLIT);
    vote_k<<<vgrid, 256>>>(hough_p);
    finish_k<<<NC, 256>>>(hough_p, rois_p, meta, ext);
}

// round 3
// speedup vs baseline: 1.6138x; 1.6138x over previous
#include <cuda_runtime.h>

#define HH 480
#define WW 640
#define NC 3
#define SKIP 5
#define PH 96            // HH/SKIP
#define PW 128           // WW/SKIP
#define NP (PH*PW)       // 12288 sampled pixels
#define BH 60            // bin rows   (GRID=8, start 4)
#define BWID 80          // bin cols
#define NB (BH*BWID)     // 4800 bins
#define BPT 4            // bins per thread (same bin row)  -- R1 proven config
#define CPG (BWID/BPT)   // 20 col-groups per bin row
#define NTH (BH*CPG)     // 1200 worker threads (bin side)
#define BGRID 5          // 5*256 = 1280 threads >= 1200
#define PSPLIT 59        // pixel-slice CTAs -> 5*59 = 295 CTAs (~2/SM)

// ---------- device scratch (no allocations allowed) ----------
__device__ float g_px[2*NP];
__device__ float g_py[2*NP];
__device__ float g_ux[2*NP];   // 2*ux
__device__ float g_uy[2*NP];   // 2*uy
__device__ float g_dd[2*NP];   // dist
__device__ int   g_n[2];       // compacted counts per class segment (class 1,2)
__device__ int   g_cnt[NC];    // raw label counts (incl. class 0)
__device__ float g_dsum[2*NB]; // dsum rows for class 1,2
__device__ float g_rois_scratch[NC*6];
__device__ float g_hough_scratch[NC*NB];

// ---------- kernel 1: zero accumulators + gather/compact sampled pixels ----------
// Zeroed arrays (hough, g_dsum) and compaction arrays are disjoint; vote_k
// (next launch) sees both completed via stream ordering.
#define PREP_TH (NC*NB)   // 14400 >= NP
__global__ void prep_k(const int* __restrict__ label,
                       const float* __restrict__ vert,
                       float* __restrict__ hough) {
    int i = blockIdx.x * blockDim.x + threadIdx.x;
    if (i < NC*NB) hough[i] = 0.0f;
    if (i < 2*NB)  g_dsum[i] = 0.0f;
    if (i < 2)     g_n[i] = 0;
    if (i < NC)    g_cnt[i] = 0;

    if (i >= NP) return;
    int r = i / PW, c = i % PW;
    int vy = r * SKIP, vx = c * SKIP;
    int vl = label[vy * WW + vx];
    atomicAdd(&g_cnt[vl], 1);
    if (vl > 0) {
        int seg  = vl - 1;
        int slot = atomicAdd(&g_n[seg], 1) + seg * NP;
        int base = (vl * 3) * (HH * WW) + vy * WW + vx;
        g_px[slot] = (float)vx;
        g_py[slot] = (float)vy;
        g_ux[slot] = 2.0f * vert[base];
        g_uy[slot] = 2.0f * vert[base + HH * WW];
        g_dd[slot] = vert[base + 2 * HH * WW];
    }
}

// NOTE on init race: g_n/g_cnt are zeroed by threads i<3 of block 0 while other
// blocks atomically increment them. Fix: zero them from host-side? Not allowed
// (no sync memcpy in capture is fine actually: cudaMemsetAsync IS allowed).
// We instead zero them in a separate tiny kernel to be safe (see launch).

__global__ void zero_small_k() {
    int i = threadIdx.x;
    if (i < 2)  g_n[i] = 0;
    if (i < NC) g_cnt[i] = 0;
}

// ---------- kernel 2: pairwise voting (R1 proven configuration) ----------
__global__ void __launch_bounds__(256, 2)
vote_k(float* __restrict__ hough) {
    __shared__ float s_px[256], s_py[256], s_ux[256], s_uy[256], s_dd[256];

    int tid = threadIdx.x;
    int gt  = blockIdx.x * 256 + tid;
    bool active = gt < NTH;
    int binrow = gt / CPG;
    int colg   = gt % CPG;
    float byf  = 4.0f + 8.0f * (float)binrow;
    float bx0  = 4.0f + 8.0f * (float)(colg * BPT);

    for (int seg = 0; seg < 2; seg++) {
        int n     = g_n[seg];
        int chunk = (n + PSPLIT - 1) / PSPLIT;
        int start = blockIdx.y * chunk;
        int end   = min(start + chunk, n);

        float aH[BPT] = {0.f, 0.f, 0.f, 0.f};
        float aD[BPT] = {0.f, 0.f, 0.f, 0.f};

        for (int t = start; t < end; t += 256) {
            int m = min(256, end - t);
            __syncthreads();
            if (tid < m) {
                int s = seg * NP + t + tid;
                s_px[tid] = g_px[s];
                s_py[tid] = g_py[s];
                s_ux[tid] = g_ux[s];
                s_uy[tid] = g_uy[s];
                s_dd[tid] = g_dd[s];
            }
            __syncthreads();

            #pragma unroll 4
            for (int j = 0; j < m; j++) {
                float px = s_px[j], py = s_py[j];
                float ux = s_ux[j], uy = s_uy[j];
                float dd = s_dd[j];
                float ddy = byf - py;
                float t2  = fmaf(ddy, ddy, 1e-6f);   // ddy^2 + eps
                float dyu = ddy * uy;                // ddy * 2uy
                #pragma unroll
                for (int b = 0; b < BPT; b++) {
                    float ddx = (bx0 + 8.0f * (float)b) - px;
                    float nxy = fmaf(ddx, ddx, t2);   // ddx^2+ddy^2+eps
                    float dot = fmaf(ddx, ux, dyu);   // 2*(ddx*ux+ddy*uy)
                    bool  ok  = (dot > 0.0f) && (dot * dot > nxy);
                    aH[b] += ok ? 1.0f : 0.0f;
                    aD[b] += ok ? dd   : 0.0f;
                }
            }
        }

        if (active) {
            int binbase = binrow * BWID + colg * BPT;
            #pragma unroll
            for (int b = 0; b < BPT; b++) {
                if (aH[b] != 0.0f) {
                    atomicAdd(&hough[(seg + 1) * NB + binbase + b], aH[b]);
                    atomicAdd(&g_dsum[seg * NB + binbase + b], aD[b]);
                }
            }
        }
        __syncthreads();
    }
}

// ---------- kernel 3: argmax + ROI epilogue (3 CTAs, one per class) ----------
__global__ void finish_k(const float* __restrict__ hough,
                         float* __restrict__ rois,
                         const float* __restrict__ meta,
                         const float* __restrict__ extents) {
    __shared__ float sv[256];
    __shared__ int   si[256];
    int c   = blockIdx.x;
    int tid = threadIdx.x;

    if (c > 0) {
        // batched loads -> high MLP (19 independent LDGs in flight)
        float best = -1.0f; int bi = 0;
        #pragma unroll
        for (int k = 0; k < 19; k++) {
            int i = tid + k * 256;
            float v = (i < NB) ? hough[c * NB + i] : -2.0f;
            if (v > best) { best = v; bi = i; }   // ascending i -> first max kept
        }
        sv[tid] = best; si[tid] = bi;
        __syncthreads();
        #pragma unroll
        for (int s = 128; s > 0; s >>= 1) {
            if (tid < s) {
                float v2 = sv[tid + s]; int i2 = si[tid + s];
                if (v2 > sv[tid] || (v2 == sv[tid] && i2 < si[tid])) {
                    sv[tid] = v2; si[tid] = i2;
                }
            }
            __syncthreads();
        }
    }

    if (tid == 0) {
        int peak; float votes;
        if (c == 0) { peak = 0; votes = 0.0f; }   // class-0 hough row is identically 0
        else        { peak = si[0]; votes = sv[0]; }
        float ds    = (c > 0) ? g_dsum[(c - 1) * NB + peak] : 0.0f;
        float depth = ds / fmaxf(votes, 1.0f);
        float cx = 4.0f + 8.0f * (float)(peak % BWID);
        float cy = 4.0f + 8.0f * (float)(peak / BWID);
        float cnt = (float)g_cnt[c];
        float score = votes / fmaxf(cnt, 1.0f);
        bool  valid = (cnt > 5.0f) && (score > 0.3f);
        float fx = meta[0], fy = meta[4];
        float e0 = extents[c*3+0], e1 = extents[c*3+1], e2 = extents[c*3+2];
        float diag = sqrtf(e0*e0 + e1*e1 + e2*e2);
        float sz = fmaxf(fabsf(depth), 0.001f);
        float bw = fabsf(diag * fx) / sz;
        float bh = fabsf(diag * fy) / sz;
        rois[c*6+0] = (float)c;
        rois[c*6+1] = cx - bw * 0.5f;
        rois[c*6+2] = cy - bh * 0.5f;
        rois[c*6+3] = cx + bw * 0.5f;
        rois[c*6+4] = cy + bh * 0.5f;
        rois[c*6+5] = valid ? score : 0.0f;
    }
}

extern "C" void kernel_launch(void* const* d_in, const int* in_sizes, int n_in,
                              void* d_out, int out_size) {
    const int*   label = (const int*)  d_in[0];
    const float* vert  = (const float*)d_in[1];
    const float* meta  = (const float*)d_in[2];
    const float* ext   = (const float*)d_in[3];
    float* out = (float*)d_out;

    // Output is the flattened tuple (rois[3,6], hough[3,4800]) -> 18 + 14400.
    float *rois_p, *hough_p;
    if (out_size >= NC*6 + NC*NB) {
        rois_p = out; hough_p = out + NC*6;
    } else if (out_size >= NC*NB) {
        void* tmp = nullptr;
        cudaGetSymbolAddress(&tmp, g_rois_scratch);
        rois_p = (float*)tmp; hough_p = out;
    } else {
        void* tmp = nullptr;
        cudaGetSymbolAddress(&tmp, g_hough_scratch);
        rois_p = out; hough_p = (float*)tmp;
    }

    zero_small_k<<<1, 32>>>();                         // counters zeroed BEFORE prep's atomics
    prep_k<<<(PREP_TH + 255) / 256, 256>>>(label, vert, hough_p);
    dim3 vgrid(BGRID, PSPLIT);
    vote_k<<<vgrid, 256>>>(hough_p);
    finish_k<<<NC, 256>>>(hough_p, rois_p, meta, ext);
}